// round 3
// baseline (speedup 1.0000x reference)
#include <cuda_runtime.h>
#include <cuda_bf16.h>
#include <math.h>

// Shapes
#define BB 4
#define NN 16384
#define DD 64
#define HH 8
#define SPLITS 16
#define CT 128               // tokens per chunk/tile
#define L2_10K 0.4152410118609203f   // log2(10000)/32

typedef unsigned long long u64;

// ---- packed f32x2 helpers (sm_103a FFMA2 path) ----
__device__ __forceinline__ u64 pk2(float a, float b) {
    u64 r;
    asm("mov.b64 %0, {%1, %2};" : "=l"(r)
        : "r"(__float_as_uint(a)), "r"(__float_as_uint(b)));
    return r;
}
__device__ __forceinline__ void fma2(u64& d, u64 a, u64 b) {
    asm("fma.rn.f32x2 %0, %1, %2, %0;" : "+l"(d) : "l"(a), "l"(b));
}
__device__ __forceinline__ float2 up2(u64 a) {
    unsigned int lo, hi;
    asm("mov.b64 {%0, %1}, %2;" : "=r"(lo), "=r"(hi) : "l"(a));
    float2 r; r.x = __uint_as_float(lo); r.y = __uint_as_float(hi);
    return r;
}
__device__ __forceinline__ float wsum(float v) {
    #pragma unroll
    for (int o = 16; o > 0; o >>= 1) v += __shfl_xor_sync(0xffffffffu, v, o);
    return v;
}

// ---- scratch (no allocation allowed) ----
__device__ float g_kv_part[BB * HH * SPLITS * DD * DD];   // 8 MB
__device__ float g_M[BB * HH * DD * DD];                  // 512 KB

// =====================================================================
// Kernel A: per (b,h,split): k/v projection + LN + RoPE + kv = k^T v
// smem floats: xs 8448 | ks 8448 | vs 8448 | wk 4096 | wv 4096 | kva 4096
// =====================================================================
__global__ __launch_bounds__(256, 1)
void kv_kernel(const float* __restrict__ x, const float* __restrict__ pos,
               const float* __restrict__ Wk, const float* __restrict__ Wv)
{
    extern __shared__ float sm[];
    float* xs  = sm;            // [128][66]
    float* ks  = sm + 8448;     // [128][66]
    float* vs  = sm + 16896;    // [128][66]
    float* wk  = sm + 25344;    // [64][64]
    float* wv  = sm + 29440;    // [64][64]
    float* kva = sm + 33536;    // [64][64]

    const int tid = threadIdx.x;
    const int b = blockIdx.z, h = blockIdx.y, s = blockIdx.x;

    // Load per-head weight slices + zero kv accumulator
    #pragma unroll
    for (int r = 0; r < 16; r++) {
        int idx = tid + r * 256;
        int i = idx >> 6, o = idx & 63;
        wk[idx]  = Wk[i * 512 + h * 64 + o];
        wv[idx]  = Wv[i * 512 + h * 64 + o];
        kva[idx] = 0.f;
    }
    __syncthreads();

    const int lane = tid & 31, w = tid >> 5;
    const float inv_freq = exp2f(-(float)lane * L2_10K);

    const int og = tid & 7,  o0 = og * 8;
    const int tg = tid >> 3, t0 = tg * 4;
    const int d0 = (tid >> 3) * 2;      // kv-phase: 2 d rows
    const int e0 = (tid & 7) * 8;       // kv-phase: 8 e cols

    const int tok_per_blk = NN / SPLITS;            // 1024
    for (int c = 0; c < tok_per_blk / CT; c++) {    // 8 chunks
        const int tbase = s * tok_per_blk + c * CT;
        const float* xg = x + ((size_t)b * NN + tbase) * 64;

        // load x tile (coalesced), padded stride 66
        #pragma unroll
        for (int r = 0; r < 32; r++) {
            int idx = tid + r * 256;
            int t = idx >> 6, i = idx & 63;
            xs[t * 66 + i] = xg[idx];
        }
        __syncthreads();

        // ---- projection: k = xWk_h, v = xWv_h  (tile 4 tokens x 8 outs, f32x2) ----
        u64 ak[4][4], av[4][4];
        #pragma unroll
        for (int j = 0; j < 4; j++)
            #pragma unroll
            for (int p = 0; p < 4; p++) { ak[j][p] = 0ull; av[j][p] = 0ull; }

        #pragma unroll 8
        for (int i = 0; i < 64; i++) {
            u64 x2[4];
            #pragma unroll
            for (int j = 0; j < 4; j++) {
                float xv = xs[(t0 + j) * 66 + i];
                x2[j] = pk2(xv, xv);
            }
            ulonglong2 wk0 = *(const ulonglong2*)&wk[i * 64 + o0];
            ulonglong2 wk1 = *(const ulonglong2*)&wk[i * 64 + o0 + 4];
            ulonglong2 wv0 = *(const ulonglong2*)&wv[i * 64 + o0];
            ulonglong2 wv1 = *(const ulonglong2*)&wv[i * 64 + o0 + 4];
            u64 wkp[4] = { wk0.x, wk0.y, wk1.x, wk1.y };
            u64 wvp[4] = { wv0.x, wv0.y, wv1.x, wv1.y };
            #pragma unroll
            for (int j = 0; j < 4; j++)
                #pragma unroll
                for (int p = 0; p < 4; p++) {
                    fma2(ak[j][p], x2[j], wkp[p]);
                    fma2(av[j][p], x2[j], wvp[p]);
                }
        }
        #pragma unroll
        for (int j = 0; j < 4; j++)
            #pragma unroll
            for (int p = 0; p < 4; p++) {
                *(u64*)&ks[(t0 + j) * 66 + o0 + 2 * p] = ak[j][p];
                *(u64*)&vs[(t0 + j) * 66 + o0 + 2 * p] = av[j][p];
            }
        __syncthreads();

        // ---- LayerNorm(k), LayerNorm(v), RoPE(k): warp per token ----
        #pragma unroll 1
        for (int r = 0; r < 16; r++) {
            int t = w * 16 + r;
            float ka = ks[t * 66 + lane],      kb = ks[t * 66 + 32 + lane];
            float va = vs[t * 66 + lane],      vb = vs[t * 66 + 32 + lane];
            float ks1 = wsum(ka + kb);
            float ks2 = wsum(ka * ka + kb * kb);
            float vs1 = wsum(va + vb);
            float vs2 = wsum(va * va + vb * vb);
            float km = ks1 * (1.f / 64.f);
            float kr = rsqrtf(fmaxf(ks2 * (1.f / 64.f) - km * km, 0.f) + 1e-5f);
            float vm = vs1 * (1.f / 64.f);
            float vr = rsqrtf(fmaxf(vs2 * (1.f / 64.f) - vm * vm, 0.f) + 1e-5f);
            float kna = (ka - km) * kr, knb = (kb - km) * kr;
            float vna = (va - vm) * vr, vnb = (vb - vm) * vr;
            float pp = pos[(size_t)b * NN + tbase + t];
            float f = pp * 64.f * inv_freq;
            float sn_, cn_;
            sincosf(f, &sn_, &cn_);
            ks[t * 66 + lane]      = kna * cn_ - knb * sn_;
            ks[t * 66 + 32 + lane] = knb * cn_ + kna * sn_;
            vs[t * 66 + lane]      = vna;
            vs[t * 66 + 32 + lane] = vnb;
        }
        __syncthreads();

        // ---- kv[d][e] += sum_t k[t][d] * v[t][e]  (tile 2d x 8e, f32x2) ----
        u64 a[2][4];
        #pragma unroll
        for (int dj = 0; dj < 2; dj++)
            #pragma unroll
            for (int p = 0; p < 4; p++)
                a[dj][p] = *(u64*)&kva[(d0 + dj) * 64 + e0 + 2 * p];

        #pragma unroll 8
        for (int t = 0; t < CT; t++) {
            float k0 = ks[t * 66 + d0], k1 = ks[t * 66 + d0 + 1];
            u64 kk0 = pk2(k0, k0), kk1 = pk2(k1, k1);
            u64 vp[4];
            #pragma unroll
            for (int p = 0; p < 4; p++)
                vp[p] = *(const u64*)&vs[t * 66 + e0 + 2 * p];
            #pragma unroll
            for (int p = 0; p < 4; p++) {
                fma2(a[0][p], kk0, vp[p]);
                fma2(a[1][p], kk1, vp[p]);
            }
        }
        #pragma unroll
        for (int dj = 0; dj < 2; dj++)
            #pragma unroll
            for (int p = 0; p < 4; p++)
                *(u64*)&kva[(d0 + dj) * 64 + e0 + 2 * p] = a[dj][p];
        __syncthreads();
    }

    // write this split's partial kv
    float* dst = g_kv_part + ((size_t)(b * HH + h) * SPLITS + s) * 4096;
    #pragma unroll
    for (int r = 0; r < 16; r++) {
        int idx = tid + r * 256;
        dst[idx] = kva[idx];
    }
}

// =====================================================================
// Kernel B: reduce kv splits, M_h = (kv_h @ Wo_h) / N
// =====================================================================
__global__ __launch_bounds__(256, 1)
void m_kernel(const float* __restrict__ Wo)
{
    __shared__ float kvs[64 * 66];
    __shared__ float wo[64 * 64];
    const int tid = threadIdx.x;
    const int h = blockIdx.x, b = blockIdx.y;
    const float* src = g_kv_part + (size_t)(b * HH + h) * SPLITS * 4096;

    #pragma unroll
    for (int r = 0; r < 16; r++) {
        int idx = tid + r * 256;
        float acc = 0.f;
        #pragma unroll
        for (int s = 0; s < SPLITS; s++) acc += src[s * 4096 + idx];
        int i = idx >> 6, j = idx & 63;
        kvs[i * 66 + j] = acc;
        wo[idx] = Wo[(h * 64 + i) * 64 + j];
    }
    __syncthreads();

    const int i0 = (tid >> 3) * 2;
    const int d0 = (tid & 7) * 8;
    u64 a[2][4];
    #pragma unroll
    for (int ij = 0; ij < 2; ij++)
        #pragma unroll
        for (int p = 0; p < 4; p++) a[ij][p] = 0ull;

    #pragma unroll 8
    for (int j = 0; j < 64; j++) {
        float k0 = kvs[i0 * 66 + j], k1 = kvs[(i0 + 1) * 66 + j];
        u64 p0 = pk2(k0, k0), p1 = pk2(k1, k1);
        u64 wp[4];
        #pragma unroll
        for (int p = 0; p < 4; p++)
            wp[p] = *(const u64*)&wo[j * 64 + d0 + 2 * p];
        #pragma unroll
        for (int p = 0; p < 4; p++) {
            fma2(a[0][p], p0, wp[p]);
            fma2(a[1][p], p1, wp[p]);
        }
    }
    const float sc = 1.f / (float)NN;
    float* dst = g_M + ((size_t)b * 512 + h * 64) * 64;
    #pragma unroll
    for (int ij = 0; ij < 2; ij++)
        #pragma unroll
        for (int p = 0; p < 4; p++) {
            float2 v = up2(a[ij][p]);
            dst[(i0 + ij) * 64 + d0 + 2 * p]     = v.x * sc;
            dst[(i0 + ij) * 64 + d0 + 2 * p + 1] = v.y * sc;
        }
}

// =====================================================================
// Kernel C: out = sum_h RoPE(x @ Wq_h) @ M_h
// smem floats: xs 8448 | qs 8448 | wq 4096 | m 4096 | cs 4096 | sn 4096
// =====================================================================
__global__ __launch_bounds__(256, 1)
void out_kernel(const float* __restrict__ x, const float* __restrict__ pos,
                const float* __restrict__ Wq, float* __restrict__ out)
{
    extern __shared__ float sm[];
    float* xs = sm;             // [128][66]
    float* qs = sm + 8448;      // [128][66]
    float* wq = sm + 16896;     // [64][64]
    float* mm = sm + 20992;     // [64][64]
    float* cs = sm + 25088;     // [128][32]
    float* sn = sm + 29184;     // [128][32]

    const int tid = threadIdx.x;
    const int b = blockIdx.y;
    const int tbase = blockIdx.x * CT;
    const float* xg = x + ((size_t)b * NN + tbase) * 64;

    #pragma unroll
    for (int r = 0; r < 32; r++) {
        int idx = tid + r * 256;
        int t = idx >> 6, i = idx & 63;
        xs[t * 66 + i] = xg[idx];
    }
    // sincos table for this tile (shared across heads)
    #pragma unroll 1
    for (int r = 0; r < 16; r++) {
        int idx = tid + r * 256;
        int t = idx >> 5, l = idx & 31;
        float pp = pos[(size_t)b * NN + tbase + t];
        float f = pp * 64.f * exp2f(-(float)l * L2_10K);
        float s_, c_;
        sincosf(f, &s_, &c_);
        cs[idx] = c_;
        sn[idx] = s_;
    }
    __syncthreads();

    const int og = tid & 7,  o0 = og * 8;
    const int tg = tid >> 3, t0 = tg * 4;
    const int lane = tid & 31, w = tid >> 5;

    u64 oa[4][4];
    #pragma unroll
    for (int j = 0; j < 4; j++)
        #pragma unroll
        for (int p = 0; p < 4; p++) oa[j][p] = 0ull;

    for (int h = 0; h < HH; h++) {
        #pragma unroll
        for (int r = 0; r < 16; r++) {
            int idx = tid + r * 256;
            int i = idx >> 6, o = idx & 63;
            wq[idx] = Wq[i * 512 + h * 64 + o];
            mm[idx] = g_M[((size_t)b * 512 + h * 64 + i) * 64 + o];
        }
        __syncthreads();

        // q = x @ Wq_h
        u64 aq[4][4];
        #pragma unroll
        for (int j = 0; j < 4; j++)
            #pragma unroll
            for (int p = 0; p < 4; p++) aq[j][p] = 0ull;

        #pragma unroll 8
        for (int i = 0; i < 64; i++) {
            u64 x2[4];
            #pragma unroll
            for (int j = 0; j < 4; j++) {
                float xv = xs[(t0 + j) * 66 + i];
                x2[j] = pk2(xv, xv);
            }
            ulonglong2 w0 = *(const ulonglong2*)&wq[i * 64 + o0];
            ulonglong2 w1 = *(const ulonglong2*)&wq[i * 64 + o0 + 4];
            u64 wp[4] = { w0.x, w0.y, w1.x, w1.y };
            #pragma unroll
            for (int j = 0; j < 4; j++)
                #pragma unroll
                for (int p = 0; p < 4; p++)
                    fma2(aq[j][p], x2[j], wp[p]);
        }
        #pragma unroll
        for (int j = 0; j < 4; j++)
            #pragma unroll
            for (int p = 0; p < 4; p++)
                *(u64*)&qs[(t0 + j) * 66 + o0 + 2 * p] = aq[j][p];
        __syncthreads();

        // RoPE(q): warp per token
        #pragma unroll 1
        for (int r = 0; r < 16; r++) {
            int t = w * 16 + r;
            float qa = qs[t * 66 + lane], qb = qs[t * 66 + 32 + lane];
            float cc = cs[t * 32 + lane], ss = sn[t * 32 + lane];
            qs[t * 66 + lane]      = qa * cc - qb * ss;
            qs[t * 66 + 32 + lane] = qb * cc + qa * ss;
        }
        __syncthreads();

        // out += q_rope @ M_h
        #pragma unroll 8
        for (int i = 0; i < 64; i++) {
            u64 q2[4];
            #pragma unroll
            for (int j = 0; j < 4; j++) {
                float qv = qs[(t0 + j) * 66 + i];
                q2[j] = pk2(qv, qv);
            }
            ulonglong2 m0 = *(const ulonglong2*)&mm[i * 64 + o0];
            ulonglong2 m1 = *(const ulonglong2*)&mm[i * 64 + o0 + 4];
            u64 mp[4] = { m0.x, m0.y, m1.x, m1.y };
            #pragma unroll
            for (int j = 0; j < 4; j++)
                #pragma unroll
                for (int p = 0; p < 4; p++)
                    fma2(oa[j][p], q2[j], mp[p]);
        }
        __syncthreads();   // protect wq/mm/qs before next head
    }

    float* outg = out + ((size_t)b * NN + tbase) * 64;
    #pragma unroll
    for (int j = 0; j < 4; j++)
        #pragma unroll
        for (int p = 0; p < 4; p++) {
            float2 v = up2(oa[j][p]);
            *(float2*)&outg[(t0 + j) * 64 + o0 + 2 * p] = v;
        }
}

// =====================================================================
extern "C" void kernel_launch(void* const* d_in, const int* in_sizes, int n_in,
                              void* d_out, int out_size)
{
    const float* x   = (const float*)d_in[0];
    const float* pos = (const float*)d_in[1];
    const float* Wq  = (const float*)d_in[2];
    const float* Wk  = (const float*)d_in[3];
    const float* Wv  = (const float*)d_in[4];
    const float* Wo  = (const float*)d_in[5];
    float* out = (float*)d_out;

    const int SMEM_A = 37632 * 4;   // 150528 B
    const int SMEM_C = 33280 * 4;   // 133120 B
    cudaFuncSetAttribute(kv_kernel,  cudaFuncAttributeMaxDynamicSharedMemorySize, SMEM_A);
    cudaFuncSetAttribute(out_kernel, cudaFuncAttributeMaxDynamicSharedMemorySize, SMEM_C);

    kv_kernel<<<dim3(SPLITS, HH, BB), 256, SMEM_A>>>(x, pos, Wk, Wv);
    m_kernel<<<dim3(HH, BB), 256>>>(Wo);
    out_kernel<<<dim3(NN / CT, BB), 256, SMEM_C>>>(x, pos, Wq, out);
}